// round 1
// baseline (speedup 1.0000x reference)
#include <cuda_runtime.h>
#include <cstdint>

#define FIN   256
#define FOUT  256
#define BATCH 65536
#define BM    64          // batch rows per CTA in GEMM pass
#define WSTRIDE 272       // padded smem row stride (bytes) -> conflict-free frag loads
#define SMEM_B (FOUT*WSTRIDE + BM*WSTRIDE)   // 87040 bytes

// ---------------- device scratch (static allocations allowed) ----------------
__device__ unsigned int g_maxbits;
__device__ float        g_params[2];            // [0]=scale_w, [1]=scale_w/15
__device__ int          g_csum [FOUT];
__device__ int          g_csum2[FOUT];
__device__ signed char  g_wq[FOUT*FIN];         // quantized weights s8
__device__ signed char  g_codes[(size_t)BATCH*FOUT]; // 16MB int8 acc codes
__device__ float4       g_bn[FOUT];             // mu, rs, gamma, beta

// ---------------- helpers ----------------
__device__ __forceinline__ void mma_u8s8(int* c, const unsigned* a, unsigned b0, unsigned b1) {
    asm volatile(
        "mma.sync.aligned.m16n8k32.row.col.s32.u8.s8.s32 "
        "{%0,%1,%2,%3},{%4,%5,%6,%7},{%8,%9},{%0,%1,%2,%3};"
        : "+r"(c[0]), "+r"(c[1]), "+r"(c[2]), "+r"(c[3])
        : "r"(a[0]), "r"(a[1]), "r"(a[2]), "r"(a[3]), "r"(b0), "r"(b1));
}

__device__ __forceinline__ unsigned qact(float v) {
    // round(clip(x,0,1)*15), round-half-even, matches jnp.round on fp32
    return (unsigned)(int)rintf(fminf(fmaxf(v, 0.0f), 1.0f) * 15.0f);
}

// ---------------- kernel A0: zero accumulators ----------------
__global__ void kA0() {
    int t = threadIdx.x;
    g_csum[t]  = 0;
    g_csum2[t] = 0;
    if (t == 0) g_maxbits = 0u;
}

// ---------------- kernel A1: max|W| reduction ----------------
__global__ void kA1(const float* __restrict__ w) {
    unsigned m = 0;
    for (int j = blockIdx.x * blockDim.x + threadIdx.x; j < FOUT * FIN;
         j += gridDim.x * blockDim.x)
        m = max(m, __float_as_uint(fabsf(w[j])));
    #pragma unroll
    for (int o = 16; o; o >>= 1) m = max(m, __shfl_xor_sync(0xffffffffu, m, o));
    __shared__ unsigned sm[8];
    if ((threadIdx.x & 31) == 0) sm[threadIdx.x >> 5] = m;
    __syncthreads();
    if (threadIdx.x < 8) {
        m = sm[threadIdx.x];
        #pragma unroll
        for (int o = 4; o; o >>= 1) m = max(m, __shfl_xor_sync(0xffu, m, o));
        if (threadIdx.x == 0) atomicMax(&g_maxbits, m);
    }
}

// ---------------- kernel A2: quantize weights ----------------
__global__ void kA2(const float* __restrict__ w) {
    float scale = __fdiv_rn(__uint_as_float(g_maxbits), 7.0f);
    if (blockIdx.x == 0 && threadIdx.x == 0) {
        g_params[0] = scale;
        g_params[1] = __fdiv_rn(scale, 15.0f);
    }
    for (int j = blockIdx.x * blockDim.x + threadIdx.x; j < FOUT * FIN;
         j += gridDim.x * blockDim.x) {
        float q = fminf(fmaxf(__fdiv_rn(w[j], scale), -7.0f), 7.0f);
        g_wq[j] = (signed char)(int)rintf(q);
    }
}

// ---------------- kernel B: quantize x + int8 GEMM + psum-quant + stats ----------------
__global__ void __launch_bounds__(256, 2) kB(const float* __restrict__ x) {
    extern __shared__ unsigned char sm[];
    unsigned char* w_s = sm;                  // [FOUT][WSTRIDE]
    unsigned char* x_s = sm + FOUT * WSTRIDE; // [BM][WSTRIDE], later reused as codes
    signed char*   codes = (signed char*)x_s; // [BM][256]

    const int tid = threadIdx.x;

    // --- load quantized weights (64KB, hits L2) ---
    const int4* wg = (const int4*)g_wq;
    #pragma unroll
    for (int i = 0; i < 16; i++) {
        int j = tid + i * 256;          // int4 idx 0..4095
        int row = j >> 4, col = j & 15;
        *(int4*)(w_s + row * WSTRIDE + col * 16) = wg[j];
    }
    // --- load + quantize activations ---
    const float4* xg = (const float4*)(x + (size_t)blockIdx.x * BM * FIN);
    #pragma unroll
    for (int i = 0; i < 16; i++) {
        int j = tid + i * 256;          // float4 idx 0..4095
        float4 v = xg[j];
        int row = j >> 6, c4 = j & 63;
        unsigned p = qact(v.x) | (qact(v.y) << 8) | (qact(v.z) << 16) | (qact(v.w) << 24);
        *(unsigned*)(x_s + row * WSTRIDE + c4 * 4) = p;
    }
    __syncthreads();

    const int warp = tid >> 5, lane = tid & 31;
    const int g = lane >> 2, tq = lane & 3;
    const int m0 = (warp & 3) * 16;     // m16 fragment base row
    const int n0 = (warp >> 2) * 128;   // 128 output channels per warp-half

    // --- preload all A fragments for this warp (2 tiles x 4 ksteps) ---
    unsigned a[8][4];
    #pragma unroll
    for (int tk = 0; tk < 8; tk++) {
        int koff = tk * 32;
        a[tk][0] = *(const unsigned*)(x_s + (m0 + g    ) * WSTRIDE + koff +      tq * 4);
        a[tk][1] = *(const unsigned*)(x_s + (m0 + g + 8) * WSTRIDE + koff +      tq * 4);
        a[tk][2] = *(const unsigned*)(x_s + (m0 + g    ) * WSTRIDE + koff + 16 + tq * 4);
        a[tk][3] = *(const unsigned*)(x_s + (m0 + g + 8) * WSTRIDE + koff + 16 + tq * 4);
    }
    __syncthreads();   // x_s region now free -> code staging

    // --- main MMA loop: 16 n-fragments, 2 crossbar tiles, 4 k-steps each ---
    #pragma unroll 2
    for (int nf = 0; nf < 16; nf++) {
        const int nrow = n0 + nf * 8 + g;        // output channel row in w_s
        int rr[4] = {0, 0, 0, 0};
        #pragma unroll
        for (int t = 0; t < 2; t++) {
            int c[4] = {0, 0, 0, 0};
            #pragma unroll
            for (int k = 0; k < 4; k++) {
                int koff = t * 128 + k * 32;
                unsigned b0 = *(const unsigned*)(w_s + nrow * WSTRIDE + koff +      tq * 4);
                unsigned b1 = *(const unsigned*)(w_s + nrow * WSTRIDE + koff + 16 + tq * 4);
                mma_u8s8(c, a[t * 4 + k], b0, b1);
            }
            // partial-sum quantization: r = round_half_even(psum / 1792) (fp32 div as ref)
            #pragma unroll
            for (int e = 0; e < 4; e++)
                rr[e] += (int)rintf(__fdiv_rn((float)c[e], 1792.0f));
        }
        // stage int8 codes: c0,c1 -> row g ; c2,c3 -> row g+8
        int col = n0 + nf * 8 + tq * 2;
        unsigned short p01 = (unsigned short)((rr[0] & 0xFF) | ((rr[1] & 0xFF) << 8));
        unsigned short p23 = (unsigned short)((rr[2] & 0xFF) | ((rr[3] & 0xFF) << 8));
        *(unsigned short*)(codes + (m0 + g    ) * 256 + col) = p01;
        *(unsigned short*)(codes + (m0 + g + 8) * 256 + col) = p23;
    }
    __syncthreads();

    // --- per-channel integer stats (exact, deterministic) ---
    int s = 0, s2 = 0;
    #pragma unroll
    for (int r = 0; r < BM; r++) {
        int v = (int)codes[r * 256 + tid];
        s += v; s2 += v * v;
    }
    atomicAdd(&g_csum [tid], s);
    atomicAdd(&g_csum2[tid], s2);

    // --- coalesced code writeout (contiguous 16KB block) ---
    int4* dst = (int4*)(g_codes + (size_t)blockIdx.x * BM * FOUT);
    const int4* src = (const int4*)codes;
    #pragma unroll
    for (int i = 0; i < 4; i++)
        dst[tid + i * 256] = src[tid + i * 256];
}

// ---------------- kernel C: finalize BN stats ----------------
__global__ void kC(const float* __restrict__ gamma, const float* __restrict__ beta) {
    int o = threadIdx.x;
    float sw15 = g_params[1];
    double C  = 1792.0 * (double)sw15;
    double s  = (double)g_csum[o];
    double s2 = (double)g_csum2[o];
    double mu = C * s / 65536.0;
    double m2 = C * C * s2 / 65536.0;
    double var = m2 - mu * mu;
    float varf = (float)var;
    float t = varf + 1e-5f;
    float rs = (float)(1.0 / sqrt((double)t));
    g_bn[o] = make_float4((float)mu, rs, gamma[o], beta[o]);
}

// ---------------- kernel D: BN + quantized clipped ReLU (elementwise) ----------------
__global__ void kD(float* __restrict__ out) {
    __shared__ float4 bn[FOUT];
    int t = threadIdx.x;
    bn[t] = g_bn[t];
    __syncthreads();
    float sw15 = g_params[1];

    size_t i4 = (size_t)blockIdx.x * 256 + t;        // char4 index, total 4194304
    char4 cc = ((const char4*)g_codes)[i4];
    int o = ((int)(i4 & 63)) * 4;

    float4 r;
    {
        int n = cc.x; float4 b = bn[o + 0];
        float acc = __fmul_rn((float)(n * 1792), sw15);
        float y = ((acc - b.x) * b.y) * b.z + b.w;
        r.x = __fdiv_rn(rintf(fminf(fmaxf(y, 0.0f), 1.0f) * 15.0f), 15.0f);
    }
    {
        int n = cc.y; float4 b = bn[o + 1];
        float acc = __fmul_rn((float)(n * 1792), sw15);
        float y = ((acc - b.x) * b.y) * b.z + b.w;
        r.y = __fdiv_rn(rintf(fminf(fmaxf(y, 0.0f), 1.0f) * 15.0f), 15.0f);
    }
    {
        int n = cc.z; float4 b = bn[o + 2];
        float acc = __fmul_rn((float)(n * 1792), sw15);
        float y = ((acc - b.x) * b.y) * b.z + b.w;
        r.z = __fdiv_rn(rintf(fminf(fmaxf(y, 0.0f), 1.0f) * 15.0f), 15.0f);
    }
    {
        int n = cc.w; float4 b = bn[o + 3];
        float acc = __fmul_rn((float)(n * 1792), sw15);
        float y = ((acc - b.x) * b.y) * b.z + b.w;
        r.w = __fdiv_rn(rintf(fminf(fmaxf(y, 0.0f), 1.0f) * 15.0f), 15.0f);
    }
    ((float4*)out)[i4] = r;
}

// ---------------- host launch ----------------
extern "C" void kernel_launch(void* const* d_in, const int* in_sizes, int n_in,
                              void* d_out, int out_size) {
    const float* x     = (const float*)d_in[0];
    const float* w     = (const float*)d_in[1];
    const float* gamma = (const float*)d_in[2];
    const float* beta  = (const float*)d_in[3];
    float* out = (float*)d_out;

    cudaFuncSetAttribute(kB, cudaFuncAttributeMaxDynamicSharedMemorySize, SMEM_B);

    kA0<<<1, 256>>>();
    kA1<<<64, 256>>>(w);
    kA2<<<64, 256>>>(w);
    kB <<<BATCH / BM, 256, SMEM_B>>>(x);
    kC <<<1, 256>>>(gamma, beta);
    kD <<<(BATCH * FOUT / 4) / 256, 256>>>(out);
    (void)in_sizes; (void)n_in; (void)out_size;
}

// round 2
// speedup vs baseline: 1.0002x; 1.0002x over previous
#include <cuda_runtime.h>
#include <cstdint>

#define FIN   256
#define FOUT  256
#define BATCH 65536
#define BM    64          // batch rows per CTA in GEMM pass
#define WSTRIDE 272       // padded smem row stride (bytes) -> conflict-free frag loads
#define SMEM_B (FOUT*WSTRIDE + BM*WSTRIDE)   // 87040 bytes

// ---------------- device scratch (static allocations allowed) ----------------
__device__ unsigned int g_maxbits;
__device__ float        g_params[2];            // [0]=scale_w, [1]=scale_w/15
__device__ int          g_csum [FOUT];
__device__ int          g_csum2[FOUT];
__device__ signed char  g_wq[FOUT*FIN];         // quantized weights s8
__device__ signed char  g_codes[(size_t)BATCH*FOUT]; // 16MB int8 acc codes
__device__ float4       g_bn[FOUT];             // mu, rs, gamma, beta

// ---------------- helpers ----------------
__device__ __forceinline__ void mma_u8s8(int* c, const unsigned* a, unsigned b0, unsigned b1) {
    asm volatile(
        "mma.sync.aligned.m16n8k32.row.col.s32.u8.s8.s32 "
        "{%0,%1,%2,%3},{%4,%5,%6,%7},{%8,%9},{%0,%1,%2,%3};"
        : "+r"(c[0]), "+r"(c[1]), "+r"(c[2]), "+r"(c[3])
        : "r"(a[0]), "r"(a[1]), "r"(a[2]), "r"(a[3]), "r"(b0), "r"(b1));
}

__device__ __forceinline__ unsigned qact(float v) {
    // round(clip(x,0,1)*15), round-half-even, matches jnp.round on fp32
    return (unsigned)(int)rintf(fminf(fmaxf(v, 0.0f), 1.0f) * 15.0f);
}

// ---------------- kernel A0: zero accumulators ----------------
__global__ void kA0() {
    int t = threadIdx.x;
    g_csum[t]  = 0;
    g_csum2[t] = 0;
    if (t == 0) g_maxbits = 0u;
}

// ---------------- kernel A1: max|W| reduction ----------------
__global__ void kA1(const float* __restrict__ w) {
    unsigned m = 0;
    for (int j = blockIdx.x * blockDim.x + threadIdx.x; j < FOUT * FIN;
         j += gridDim.x * blockDim.x)
        m = max(m, __float_as_uint(fabsf(w[j])));
    #pragma unroll
    for (int o = 16; o; o >>= 1) m = max(m, __shfl_xor_sync(0xffffffffu, m, o));
    __shared__ unsigned sm[8];
    if ((threadIdx.x & 31) == 0) sm[threadIdx.x >> 5] = m;
    __syncthreads();
    if (threadIdx.x < 8) {
        m = sm[threadIdx.x];
        #pragma unroll
        for (int o = 4; o; o >>= 1) m = max(m, __shfl_xor_sync(0xffu, m, o));
        if (threadIdx.x == 0) atomicMax(&g_maxbits, m);
    }
}

// ---------------- kernel A2: quantize weights ----------------
__global__ void kA2(const float* __restrict__ w) {
    float scale = __fdiv_rn(__uint_as_float(g_maxbits), 7.0f);
    if (blockIdx.x == 0 && threadIdx.x == 0) {
        g_params[0] = scale;
        g_params[1] = __fdiv_rn(scale, 15.0f);
    }
    for (int j = blockIdx.x * blockDim.x + threadIdx.x; j < FOUT * FIN;
         j += gridDim.x * blockDim.x) {
        float q = fminf(fmaxf(__fdiv_rn(w[j], scale), -7.0f), 7.0f);
        g_wq[j] = (signed char)(int)rintf(q);
    }
}

// ---------------- kernel B: quantize x + int8 GEMM + psum-quant + stats ----------------
__global__ void __launch_bounds__(256, 2) kB(const float* __restrict__ x) {
    extern __shared__ unsigned char sm[];
    unsigned char* w_s = sm;                  // [FOUT][WSTRIDE]
    unsigned char* x_s = sm + FOUT * WSTRIDE; // [BM][WSTRIDE], later reused as codes
    signed char*   codes = (signed char*)x_s; // [BM][256]

    const int tid = threadIdx.x;

    // --- load quantized weights (64KB, hits L2) ---
    const int4* wg = (const int4*)g_wq;
    #pragma unroll
    for (int i = 0; i < 16; i++) {
        int j = tid + i * 256;          // int4 idx 0..4095
        int row = j >> 4, col = j & 15;
        *(int4*)(w_s + row * WSTRIDE + col * 16) = wg[j];
    }
    // --- load + quantize activations ---
    const float4* xg = (const float4*)(x + (size_t)blockIdx.x * BM * FIN);
    #pragma unroll
    for (int i = 0; i < 16; i++) {
        int j = tid + i * 256;          // float4 idx 0..4095
        float4 v = xg[j];
        int row = j >> 6, c4 = j & 63;
        unsigned p = qact(v.x) | (qact(v.y) << 8) | (qact(v.z) << 16) | (qact(v.w) << 24);
        *(unsigned*)(x_s + row * WSTRIDE + c4 * 4) = p;
    }
    __syncthreads();

    const int warp = tid >> 5, lane = tid & 31;
    const int g = lane >> 2, tq = lane & 3;
    const int m0 = (warp & 3) * 16;     // m16 fragment base row
    const int n0 = (warp >> 2) * 128;   // 128 output channels per warp-half

    // --- preload all A fragments for this warp (2 tiles x 4 ksteps) ---
    unsigned a[8][4];
    #pragma unroll
    for (int tk = 0; tk < 8; tk++) {
        int koff = tk * 32;
        a[tk][0] = *(const unsigned*)(x_s + (m0 + g    ) * WSTRIDE + koff +      tq * 4);
        a[tk][1] = *(const unsigned*)(x_s + (m0 + g + 8) * WSTRIDE + koff +      tq * 4);
        a[tk][2] = *(const unsigned*)(x_s + (m0 + g    ) * WSTRIDE + koff + 16 + tq * 4);
        a[tk][3] = *(const unsigned*)(x_s + (m0 + g + 8) * WSTRIDE + koff + 16 + tq * 4);
    }
    __syncthreads();   // x_s region now free -> code staging

    // --- main MMA loop: 16 n-fragments, 2 crossbar tiles, 4 k-steps each ---
    #pragma unroll 2
    for (int nf = 0; nf < 16; nf++) {
        const int nrow = n0 + nf * 8 + g;        // output channel row in w_s
        int rr[4] = {0, 0, 0, 0};
        #pragma unroll
        for (int t = 0; t < 2; t++) {
            int c[4] = {0, 0, 0, 0};
            #pragma unroll
            for (int k = 0; k < 4; k++) {
                int koff = t * 128 + k * 32;
                unsigned b0 = *(const unsigned*)(w_s + nrow * WSTRIDE + koff +      tq * 4);
                unsigned b1 = *(const unsigned*)(w_s + nrow * WSTRIDE + koff + 16 + tq * 4);
                mma_u8s8(c, a[t * 4 + k], b0, b1);
            }
            // partial-sum quantization: r = round_half_even(psum / 1792) (fp32 div as ref)
            #pragma unroll
            for (int e = 0; e < 4; e++)
                rr[e] += (int)rintf(__fdiv_rn((float)c[e], 1792.0f));
        }
        // stage int8 codes: c0,c1 -> row g ; c2,c3 -> row g+8
        int col = n0 + nf * 8 + tq * 2;
        unsigned short p01 = (unsigned short)((rr[0] & 0xFF) | ((rr[1] & 0xFF) << 8));
        unsigned short p23 = (unsigned short)((rr[2] & 0xFF) | ((rr[3] & 0xFF) << 8));
        *(unsigned short*)(codes + (m0 + g    ) * 256 + col) = p01;
        *(unsigned short*)(codes + (m0 + g + 8) * 256 + col) = p23;
    }
    __syncthreads();

    // --- per-channel integer stats (exact, deterministic) ---
    int s = 0, s2 = 0;
    #pragma unroll
    for (int r = 0; r < BM; r++) {
        int v = (int)codes[r * 256 + tid];
        s += v; s2 += v * v;
    }
    atomicAdd(&g_csum [tid], s);
    atomicAdd(&g_csum2[tid], s2);

    // --- coalesced code writeout (contiguous 16KB block) ---
    int4* dst = (int4*)(g_codes + (size_t)blockIdx.x * BM * FOUT);
    const int4* src = (const int4*)codes;
    #pragma unroll
    for (int i = 0; i < 4; i++)
        dst[tid + i * 256] = src[tid + i * 256];
}

// ---------------- kernel C: finalize BN stats ----------------
__global__ void kC(const float* __restrict__ gamma, const float* __restrict__ beta) {
    int o = threadIdx.x;
    float sw15 = g_params[1];
    double C  = 1792.0 * (double)sw15;
    double s  = (double)g_csum[o];
    double s2 = (double)g_csum2[o];
    double mu = C * s / 65536.0;
    double m2 = C * C * s2 / 65536.0;
    double var = m2 - mu * mu;
    float varf = (float)var;
    float t = varf + 1e-5f;
    float rs = (float)(1.0 / sqrt((double)t));
    g_bn[o] = make_float4((float)mu, rs, gamma[o], beta[o]);
}

// ---------------- kernel D: BN + quantized clipped ReLU (elementwise) ----------------
__global__ void kD(float* __restrict__ out) {
    __shared__ float4 bn[FOUT];
    int t = threadIdx.x;
    bn[t] = g_bn[t];
    __syncthreads();
    float sw15 = g_params[1];

    size_t i4 = (size_t)blockIdx.x * 256 + t;        // char4 index, total 4194304
    char4 cc = ((const char4*)g_codes)[i4];
    int o = ((int)(i4 & 63)) * 4;

    float4 r;
    {
        int n = cc.x; float4 b = bn[o + 0];
        float acc = __fmul_rn((float)(n * 1792), sw15);
        float y = ((acc - b.x) * b.y) * b.z + b.w;
        r.x = __fdiv_rn(rintf(fminf(fmaxf(y, 0.0f), 1.0f) * 15.0f), 15.0f);
    }
    {
        int n = cc.y; float4 b = bn[o + 1];
        float acc = __fmul_rn((float)(n * 1792), sw15);
        float y = ((acc - b.x) * b.y) * b.z + b.w;
        r.y = __fdiv_rn(rintf(fminf(fmaxf(y, 0.0f), 1.0f) * 15.0f), 15.0f);
    }
    {
        int n = cc.z; float4 b = bn[o + 2];
        float acc = __fmul_rn((float)(n * 1792), sw15);
        float y = ((acc - b.x) * b.y) * b.z + b.w;
        r.z = __fdiv_rn(rintf(fminf(fmaxf(y, 0.0f), 1.0f) * 15.0f), 15.0f);
    }
    {
        int n = cc.w; float4 b = bn[o + 3];
        float acc = __fmul_rn((float)(n * 1792), sw15);
        float y = ((acc - b.x) * b.y) * b.z + b.w;
        r.w = __fdiv_rn(rintf(fminf(fmaxf(y, 0.0f), 1.0f) * 15.0f), 15.0f);
    }
    ((float4*)out)[i4] = r;
}

// ---------------- host launch ----------------
extern "C" void kernel_launch(void* const* d_in, const int* in_sizes, int n_in,
                              void* d_out, int out_size) {
    const float* x     = (const float*)d_in[0];
    const float* w     = (const float*)d_in[1];
    const float* gamma = (const float*)d_in[2];
    const float* beta  = (const float*)d_in[3];
    float* out = (float*)d_out;

    cudaFuncSetAttribute(kB, cudaFuncAttributeMaxDynamicSharedMemorySize, SMEM_B);

    kA0<<<1, 256>>>();
    kA1<<<64, 256>>>(w);
    kA2<<<64, 256>>>(w);
    kB <<<BATCH / BM, 256, SMEM_B>>>(x);
    kC <<<1, 256>>>(gamma, beta);
    kD <<<(BATCH * FOUT / 4) / 256, 256>>>(out);
    (void)in_sizes; (void)n_in; (void)out_size;
}